// round 2
// baseline (speedup 1.0000x reference)
#include <cuda_runtime.h>
#include <cuda_bf16.h>

// Shapes (fixed for this problem)
#define B_  2
#define T_  2048
#define C_  2048          // d_model
#define H_  16
#define DH_ 128           // head dim
#define BT_ (B_ * T_)     // 4096 rows
#define QKV_C (3 * C_)    // 6144

// Scratch (device globals — no allocation)
__device__ float g_qkv[(size_t)B_ * T_ * QKV_C];  // 96 MB
__device__ float g_y[(size_t)B_ * T_ * C_];       // 32 MB

// ============================================================================
// SGEMM: C[M,N] = A[M,K] @ B[N,K]^T   (A, B row-major; K contiguous in both)
// 128x128 block tile, BK=8, 256 threads, 8x8 per thread.
// ============================================================================
#define BM 128
#define BN 128
#define BK 8
#define TM 8
#define TN 8

__global__ __launch_bounds__(256, 2)
void sgemm_nt(const float* __restrict__ A, const float* __restrict__ Bm,
              float* __restrict__ C, int M, int N, int K) {
    __shared__ float As[BK][BM];
    __shared__ float Bs[BK][BN];

    const int tid = threadIdx.x;
    const int ty = tid >> 4;          // 0..15
    const int tx = tid & 15;          // 0..15
    const int bm = blockIdx.y * BM;
    const int bn = blockIdx.x * BN;

    // global-load mapping: one float4 of A and one of B per thread per k-tile
    const int lrow = tid >> 1;        // 0..127
    const int lcol = (tid & 1) * 4;   // 0 or 4

    const float* Ab = A + (size_t)bm * K;
    const float* Bb = Bm + (size_t)bn * K;

    float acc[TM][TN];
    #pragma unroll
    for (int i = 0; i < TM; i++)
        #pragma unroll
        for (int j = 0; j < TN; j++) acc[i][j] = 0.f;

    for (int k0 = 0; k0 < K; k0 += BK) {
        float4 av = *(const float4*)(Ab + (size_t)lrow * K + k0 + lcol);
        float4 bv = *(const float4*)(Bb + (size_t)lrow * K + k0 + lcol);
        As[lcol + 0][lrow] = av.x; As[lcol + 1][lrow] = av.y;
        As[lcol + 2][lrow] = av.z; As[lcol + 3][lrow] = av.w;
        Bs[lcol + 0][lrow] = bv.x; Bs[lcol + 1][lrow] = bv.y;
        Bs[lcol + 2][lrow] = bv.z; Bs[lcol + 3][lrow] = bv.w;
        __syncthreads();

        #pragma unroll
        for (int kk = 0; kk < BK; kk++) {
            float a[TM], b[TN];
            float4 a0 = *(const float4*)&As[kk][ty * TM];
            float4 a1 = *(const float4*)&As[kk][ty * TM + 4];
            float4 b0 = *(const float4*)&Bs[kk][tx * TN];
            float4 b1 = *(const float4*)&Bs[kk][tx * TN + 4];
            a[0]=a0.x; a[1]=a0.y; a[2]=a0.z; a[3]=a0.w;
            a[4]=a1.x; a[5]=a1.y; a[6]=a1.z; a[7]=a1.w;
            b[0]=b0.x; b[1]=b0.y; b[2]=b0.z; b[3]=b0.w;
            b[4]=b1.x; b[5]=b1.y; b[6]=b1.z; b[7]=b1.w;
            #pragma unroll
            for (int i = 0; i < TM; i++)
                #pragma unroll
                for (int j = 0; j < TN; j++)
                    acc[i][j] = fmaf(a[i], b[j], acc[i][j]);
        }
        __syncthreads();
    }

    #pragma unroll
    for (int i = 0; i < TM; i++) {
        float* crow = C + (size_t)(bm + ty * TM + i) * N + bn + tx * TN;
        ((float4*)crow)[0] = make_float4(acc[i][0], acc[i][1], acc[i][2], acc[i][3]);
        ((float4*)crow)[1] = make_float4(acc[i][4], acc[i][5], acc[i][6], acc[i][7]);
    }
}

// ============================================================================
// Flash attention (causal, online softmax), fp32.
// grid: (T/64, H, B), 256 threads (16x16). Q-tile 64x128, K-tile 64.
// smem strides padded: QKV rows 132 floats (8-way max conflict on K-col reads),
// S rows 65 floats (conflict-free row scans).
// ============================================================================
#define FROWS 64
#define QSTRIDE 132
#define SSTRIDE 65

extern __shared__ float fsm[];

__global__ __launch_bounds__(256, 1)
void flash_attn(const float* __restrict__ qkv, float* __restrict__ y) {
    const int qt = blockIdx.x;
    const int h  = blockIdx.y;
    const int b  = blockIdx.z;
    const int tid = threadIdx.x;
    const int ty = tid >> 4;   // 0..15  (row group of 4)
    const int tx = tid & 15;   // 0..15

    float* Qs = fsm;                       // [64][132]
    float* Ks = Qs + FROWS * QSTRIDE;      // [64][132]
    float* Vs = Ks + FROWS * QSTRIDE;      // [64][132]
    float* Ss = Vs + FROWS * QSTRIDE;      // [64][65]
    float* ms = Ss + FROWS * SSTRIDE;      // [64]
    float* ls = ms + FROWS;                // [64]
    float* rs = ls + FROWS;                // [64]

    const float scale = 0.08838834764831845f;  // 1/sqrt(128)

    const float* qb = qkv + ((size_t)b * T_) * QKV_C + h * DH_;
    const float* kb = qb + C_;
    const float* vb = qb + 2 * C_;

    // Load Q tile: 64 rows x 128 floats = 2048 float4 / 256 thr = 8 each
    for (int i = tid; i < FROWS * 32; i += 256) {
        int r = i >> 5, c4 = i & 31;
        *(float4*)(Qs + r * QSTRIDE + c4 * 4) =
            ((const float4*)(qb + (size_t)(qt * FROWS + r) * QKV_C))[c4];
    }
    if (tid < FROWS) { ms[tid] = -1e30f; ls[tid] = 0.f; }

    float o[4][8];
    #pragma unroll
    for (int i = 0; i < 4; i++)
        #pragma unroll
        for (int j = 0; j < 8; j++) o[i][j] = 0.f;

    for (int kt = 0; kt <= qt; kt++) {
        __syncthreads();   // protects Ss/Ks/Vs from previous iter + Q/stats on iter 0
        for (int i = tid; i < FROWS * 32; i += 256) {
            int r = i >> 5, c4 = i & 31;
            *(float4*)(Ks + r * QSTRIDE + c4 * 4) =
                ((const float4*)(kb + (size_t)(kt * FROWS + r) * QKV_C))[c4];
            *(float4*)(Vs + r * QSTRIDE + c4 * 4) =
                ((const float4*)(vb + (size_t)(kt * FROWS + r) * QKV_C))[c4];
        }
        __syncthreads();

        // ---- S = Q K^T (thread: rows ty*4.., cols tx*4..) ----
        float s[4][4];
        #pragma unroll
        for (int i = 0; i < 4; i++)
            #pragma unroll
            for (int j = 0; j < 4; j++) s[i][j] = 0.f;

        for (int d4 = 0; d4 < 32; d4++) {
            float4 qv[4], kv[4];
            #pragma unroll
            for (int i = 0; i < 4; i++)
                qv[i] = *(const float4*)(Qs + (ty * 4 + i) * QSTRIDE + d4 * 4);
            #pragma unroll
            for (int j = 0; j < 4; j++)
                kv[j] = *(const float4*)(Ks + (tx * 4 + j) * QSTRIDE + d4 * 4);
            #pragma unroll
            for (int i = 0; i < 4; i++)
                #pragma unroll
                for (int j = 0; j < 4; j++) {
                    s[i][j] = fmaf(qv[i].x, kv[j].x, s[i][j]);
                    s[i][j] = fmaf(qv[i].y, kv[j].y, s[i][j]);
                    s[i][j] = fmaf(qv[i].z, kv[j].z, s[i][j]);
                    s[i][j] = fmaf(qv[i].w, kv[j].w, s[i][j]);
                }
        }

        // scale + causal mask, write to Ss
        #pragma unroll
        for (int i = 0; i < 4; i++) {
            int gq = qt * FROWS + ty * 4 + i;
            #pragma unroll
            for (int j = 0; j < 4; j++) {
                int gk = kt * FROWS + tx * 4 + j;
                float v = s[i][j] * scale;
                if (gk > gq) v = -1e30f;
                Ss[(ty * 4 + i) * SSTRIDE + tx * 4 + j] = v;
            }
        }
        __syncthreads();

        // ---- online softmax, one thread per row ----
        if (tid < FROWS) {
            float mold = ms[tid];
            float mloc = mold;
            float* row = Ss + tid * SSTRIDE;
            #pragma unroll 8
            for (int c = 0; c < FROWS; c++) mloc = fmaxf(mloc, row[c]);
            float rsc = __expf(mold - mloc);
            float sum = 0.f;
            #pragma unroll 8
            for (int c = 0; c < FROWS; c++) {
                float p = __expf(row[c] - mloc);
                row[c] = p;
                sum += p;
            }
            ms[tid] = mloc;
            ls[tid] = ls[tid] * rsc + sum;
            rs[tid] = rsc;
        }
        __syncthreads();

        // ---- rescale O, accumulate O += P @ V (thread cols tx*8..) ----
        #pragma unroll
        for (int i = 0; i < 4; i++) {
            float f = rs[ty * 4 + i];
            #pragma unroll
            for (int j = 0; j < 8; j++) o[i][j] *= f;
        }
        for (int kk = 0; kk < FROWS; kk++) {
            float p[4];
            #pragma unroll
            for (int i = 0; i < 4; i++) p[i] = Ss[(ty * 4 + i) * SSTRIDE + kk];
            float4 v0 = *(const float4*)(Vs + kk * QSTRIDE + tx * 8);
            float4 v1 = *(const float4*)(Vs + kk * QSTRIDE + tx * 8 + 4);
            #pragma unroll
            for (int i = 0; i < 4; i++) {
                o[i][0] = fmaf(p[i], v0.x, o[i][0]);
                o[i][1] = fmaf(p[i], v0.y, o[i][1]);
                o[i][2] = fmaf(p[i], v0.z, o[i][2]);
                o[i][3] = fmaf(p[i], v0.w, o[i][3]);
                o[i][4] = fmaf(p[i], v1.x, o[i][4]);
                o[i][5] = fmaf(p[i], v1.y, o[i][5]);
                o[i][6] = fmaf(p[i], v1.z, o[i][6]);
                o[i][7] = fmaf(p[i], v1.w, o[i][7]);
            }
        }
    }
    __syncthreads();

    // write y[b, t, h*128 + col]  (BTC layout, ready for proj GEMM)
    #pragma unroll
    for (int i = 0; i < 4; i++) {
        int r = ty * 4 + i;
        float inv = 1.0f / ls[r];
        float* yrow = y + ((size_t)b * T_ + qt * FROWS + r) * C_ + h * DH_ + tx * 8;
        ((float4*)yrow)[0] = make_float4(o[i][0]*inv, o[i][1]*inv, o[i][2]*inv, o[i][3]*inv);
        ((float4*)yrow)[1] = make_float4(o[i][4]*inv, o[i][5]*inv, o[i][6]*inv, o[i][7]*inv);
    }
}

// ============================================================================
// launch
// ============================================================================
static const int FLASH_SMEM =
    (3 * FROWS * QSTRIDE + FROWS * SSTRIDE + 3 * FROWS) * (int)sizeof(float);

extern "C" void kernel_launch(void* const* d_in, const int* in_sizes, int n_in,
                              void* d_out, int out_size) {
    const float* x     = (const float*)d_in[0];   // [2,2048,2048]
    const float* Wqkv  = (const float*)d_in[1];   // [6144,2048]
    const float* Wproj = (const float*)d_in[2];   // [2048,2048]
    float* out = (float*)d_out;                   // [2,2048,2048]

    float* qkv = nullptr;
    float* y = nullptr;
    cudaGetSymbolAddress((void**)&qkv, g_qkv);
    cudaGetSymbolAddress((void**)&y, g_y);

    cudaFuncSetAttribute(flash_attn, cudaFuncAttributeMaxDynamicSharedMemorySize,
                         FLASH_SMEM);

    // 1) qkv = x @ Wqkv^T : [4096,2048] x [6144,2048]^T
    {
        dim3 grid(QKV_C / BN, BT_ / BM);
        sgemm_nt<<<grid, 256>>>(x, Wqkv, qkv, BT_, QKV_C, C_);
    }
    // 2) flash attention -> y [B,T,C]
    {
        dim3 grid(T_ / FROWS, H_, B_);
        flash_attn<<<grid, 256, FLASH_SMEM>>>(qkv, y);
    }
    // 3) out = y @ Wproj^T : [4096,2048] x [2048,2048]^T
    {
        dim3 grid(C_ / BN, BT_ / BM);
        sgemm_nt<<<grid, 256>>>(y, Wproj, out, BT_, C_, C_);
    }
}

// round 3
// speedup vs baseline: 1.0004x; 1.0004x over previous
#include <cuda_runtime.h>
#include <cuda_bf16.h>

// Shapes (fixed for this problem)
#define B_  2
#define T_  2048
#define C_  2048          // d_model
#define H_  16
#define DH_ 128           // head dim
#define BT_ (B_ * T_)     // 4096 rows
#define QKV_C (3 * C_)    // 6144

// Scratch (device globals — no allocation)
__device__ float g_qkv[(size_t)B_ * T_ * QKV_C];  // 96 MB
__device__ float g_y[(size_t)B_ * T_ * C_];       // 32 MB

// ============================================================================
// SGEMM: C[M,N] = A[M,K] @ B[N,K]^T   (A, B row-major; K contiguous in both)
// 128x128 block tile, BK=8, 256 threads, 8x8 per thread.
// ============================================================================
#define BM 128
#define BN 128
#define BK 8
#define TM 8
#define TN 8

__global__ __launch_bounds__(256, 2)
void sgemm_nt(const float* __restrict__ A, const float* __restrict__ Bm,
              float* __restrict__ C, int M, int N, int K) {
    __shared__ float As[BK][BM];
    __shared__ float Bs[BK][BN];

    const int tid = threadIdx.x;
    const int ty = tid >> 4;          // 0..15
    const int tx = tid & 15;          // 0..15
    const int bm = blockIdx.y * BM;
    const int bn = blockIdx.x * BN;

    // global-load mapping: one float4 of A and one of B per thread per k-tile
    const int lrow = tid >> 1;        // 0..127
    const int lcol = (tid & 1) * 4;   // 0 or 4

    const float* Ab = A + (size_t)bm * K;
    const float* Bb = Bm + (size_t)bn * K;

    float acc[TM][TN];
    #pragma unroll
    for (int i = 0; i < TM; i++)
        #pragma unroll
        for (int j = 0; j < TN; j++) acc[i][j] = 0.f;

    for (int k0 = 0; k0 < K; k0 += BK) {
        float4 av = *(const float4*)(Ab + (size_t)lrow * K + k0 + lcol);
        float4 bv = *(const float4*)(Bb + (size_t)lrow * K + k0 + lcol);
        As[lcol + 0][lrow] = av.x; As[lcol + 1][lrow] = av.y;
        As[lcol + 2][lrow] = av.z; As[lcol + 3][lrow] = av.w;
        Bs[lcol + 0][lrow] = bv.x; Bs[lcol + 1][lrow] = bv.y;
        Bs[lcol + 2][lrow] = bv.z; Bs[lcol + 3][lrow] = bv.w;
        __syncthreads();

        #pragma unroll
        for (int kk = 0; kk < BK; kk++) {
            float a[TM], b[TN];
            float4 a0 = *(const float4*)&As[kk][ty * TM];
            float4 a1 = *(const float4*)&As[kk][ty * TM + 4];
            float4 b0 = *(const float4*)&Bs[kk][tx * TN];
            float4 b1 = *(const float4*)&Bs[kk][tx * TN + 4];
            a[0]=a0.x; a[1]=a0.y; a[2]=a0.z; a[3]=a0.w;
            a[4]=a1.x; a[5]=a1.y; a[6]=a1.z; a[7]=a1.w;
            b[0]=b0.x; b[1]=b0.y; b[2]=b0.z; b[3]=b0.w;
            b[4]=b1.x; b[5]=b1.y; b[6]=b1.z; b[7]=b1.w;
            #pragma unroll
            for (int i = 0; i < TM; i++)
                #pragma unroll
                for (int j = 0; j < TN; j++)
                    acc[i][j] = fmaf(a[i], b[j], acc[i][j]);
        }
        __syncthreads();
    }

    #pragma unroll
    for (int i = 0; i < TM; i++) {
        float* crow = C + (size_t)(bm + ty * TM + i) * N + bn + tx * TN;
        ((float4*)crow)[0] = make_float4(acc[i][0], acc[i][1], acc[i][2], acc[i][3]);
        ((float4*)crow)[1] = make_float4(acc[i][4], acc[i][5], acc[i][6], acc[i][7]);
    }
}

// ============================================================================
// Flash attention (causal, online softmax), fp32.
// grid: (T/64, H, B), 256 threads (16x16). Q-tile 64x128, K-tile 64.
// smem strides padded: QKV rows 132 floats (8-way max conflict on K-col reads),
// S rows 65 floats (conflict-free row scans).
// ============================================================================
#define FROWS 64
#define QSTRIDE 132
#define SSTRIDE 65

extern __shared__ float fsm[];

__global__ __launch_bounds__(256, 1)
void flash_attn(const float* __restrict__ qkv, float* __restrict__ y) {
    const int qt = blockIdx.x;
    const int h  = blockIdx.y;
    const int b  = blockIdx.z;
    const int tid = threadIdx.x;
    const int ty = tid >> 4;   // 0..15  (row group of 4)
    const int tx = tid & 15;   // 0..15

    float* Qs = fsm;                       // [64][132]
    float* Ks = Qs + FROWS * QSTRIDE;      // [64][132]
    float* Vs = Ks + FROWS * QSTRIDE;      // [64][132]
    float* Ss = Vs + FROWS * QSTRIDE;      // [64][65]
    float* ms = Ss + FROWS * SSTRIDE;      // [64]
    float* ls = ms + FROWS;                // [64]
    float* rs = ls + FROWS;                // [64]

    const float scale = 0.08838834764831845f;  // 1/sqrt(128)

    const float* qb = qkv + ((size_t)b * T_) * QKV_C + h * DH_;
    const float* kb = qb + C_;
    const float* vb = qb + 2 * C_;

    // Load Q tile: 64 rows x 128 floats = 2048 float4 / 256 thr = 8 each
    for (int i = tid; i < FROWS * 32; i += 256) {
        int r = i >> 5, c4 = i & 31;
        *(float4*)(Qs + r * QSTRIDE + c4 * 4) =
            ((const float4*)(qb + (size_t)(qt * FROWS + r) * QKV_C))[c4];
    }
    if (tid < FROWS) { ms[tid] = -1e30f; ls[tid] = 0.f; }

    float o[4][8];
    #pragma unroll
    for (int i = 0; i < 4; i++)
        #pragma unroll
        for (int j = 0; j < 8; j++) o[i][j] = 0.f;

    for (int kt = 0; kt <= qt; kt++) {
        __syncthreads();   // protects Ss/Ks/Vs from previous iter + Q/stats on iter 0
        for (int i = tid; i < FROWS * 32; i += 256) {
            int r = i >> 5, c4 = i & 31;
            *(float4*)(Ks + r * QSTRIDE + c4 * 4) =
                ((const float4*)(kb + (size_t)(kt * FROWS + r) * QKV_C))[c4];
            *(float4*)(Vs + r * QSTRIDE + c4 * 4) =
                ((const float4*)(vb + (size_t)(kt * FROWS + r) * QKV_C))[c4];
        }
        __syncthreads();

        // ---- S = Q K^T (thread: rows ty*4.., cols tx*4..) ----
        float s[4][4];
        #pragma unroll
        for (int i = 0; i < 4; i++)
            #pragma unroll
            for (int j = 0; j < 4; j++) s[i][j] = 0.f;

        for (int d4 = 0; d4 < 32; d4++) {
            float4 qv[4], kv[4];
            #pragma unroll
            for (int i = 0; i < 4; i++)
                qv[i] = *(const float4*)(Qs + (ty * 4 + i) * QSTRIDE + d4 * 4);
            #pragma unroll
            for (int j = 0; j < 4; j++)
                kv[j] = *(const float4*)(Ks + (tx * 4 + j) * QSTRIDE + d4 * 4);
            #pragma unroll
            for (int i = 0; i < 4; i++)
                #pragma unroll
                for (int j = 0; j < 4; j++) {
                    s[i][j] = fmaf(qv[i].x, kv[j].x, s[i][j]);
                    s[i][j] = fmaf(qv[i].y, kv[j].y, s[i][j]);
                    s[i][j] = fmaf(qv[i].z, kv[j].z, s[i][j]);
                    s[i][j] = fmaf(qv[i].w, kv[j].w, s[i][j]);
                }
        }

        // scale + causal mask, write to Ss
        #pragma unroll
        for (int i = 0; i < 4; i++) {
            int gq = qt * FROWS + ty * 4 + i;
            #pragma unroll
            for (int j = 0; j < 4; j++) {
                int gk = kt * FROWS + tx * 4 + j;
                float v = s[i][j] * scale;
                if (gk > gq) v = -1e30f;
                Ss[(ty * 4 + i) * SSTRIDE + tx * 4 + j] = v;
            }
        }
        __syncthreads();

        // ---- online softmax, one thread per row ----
        if (tid < FROWS) {
            float mold = ms[tid];
            float mloc = mold;
            float* row = Ss + tid * SSTRIDE;
            #pragma unroll 8
            for (int c = 0; c < FROWS; c++) mloc = fmaxf(mloc, row[c]);
            float rsc = __expf(mold - mloc);
            float sum = 0.f;
            #pragma unroll 8
            for (int c = 0; c < FROWS; c++) {
                float p = __expf(row[c] - mloc);
                row[c] = p;
                sum += p;
            }
            ms[tid] = mloc;
            ls[tid] = ls[tid] * rsc + sum;
            rs[tid] = rsc;
        }
        __syncthreads();

        // ---- rescale O, accumulate O += P @ V (thread cols tx*8..) ----
        #pragma unroll
        for (int i = 0; i < 4; i++) {
            float f = rs[ty * 4 + i];
            #pragma unroll
            for (int j = 0; j < 8; j++) o[i][j] *= f;
        }
        for (int kk = 0; kk < FROWS; kk++) {
            float p[4];
            #pragma unroll
            for (int i = 0; i < 4; i++) p[i] = Ss[(ty * 4 + i) * SSTRIDE + kk];
            float4 v0 = *(const float4*)(Vs + kk * QSTRIDE + tx * 8);
            float4 v1 = *(const float4*)(Vs + kk * QSTRIDE + tx * 8 + 4);
            #pragma unroll
            for (int i = 0; i < 4; i++) {
                o[i][0] = fmaf(p[i], v0.x, o[i][0]);
                o[i][1] = fmaf(p[i], v0.y, o[i][1]);
                o[i][2] = fmaf(p[i], v0.z, o[i][2]);
                o[i][3] = fmaf(p[i], v0.w, o[i][3]);
                o[i][4] = fmaf(p[i], v1.x, o[i][4]);
                o[i][5] = fmaf(p[i], v1.y, o[i][5]);
                o[i][6] = fmaf(p[i], v1.z, o[i][6]);
                o[i][7] = fmaf(p[i], v1.w, o[i][7]);
            }
        }
    }
    __syncthreads();

    // write y[b, t, h*128 + col]  (BTC layout, ready for proj GEMM)
    #pragma unroll
    for (int i = 0; i < 4; i++) {
        int r = ty * 4 + i;
        float inv = 1.0f / ls[r];
        float* yrow = y + ((size_t)b * T_ + qt * FROWS + r) * C_ + h * DH_ + tx * 8;
        ((float4*)yrow)[0] = make_float4(o[i][0]*inv, o[i][1]*inv, o[i][2]*inv, o[i][3]*inv);
        ((float4*)yrow)[1] = make_float4(o[i][4]*inv, o[i][5]*inv, o[i][6]*inv, o[i][7]*inv);
    }
}

// ============================================================================
// launch
// ============================================================================
static const int FLASH_SMEM =
    (3 * FROWS * QSTRIDE + FROWS * SSTRIDE + 3 * FROWS) * (int)sizeof(float);

extern "C" void kernel_launch(void* const* d_in, const int* in_sizes, int n_in,
                              void* d_out, int out_size) {
    const float* x     = (const float*)d_in[0];   // [2,2048,2048]
    const float* Wqkv  = (const float*)d_in[1];   // [6144,2048]
    const float* Wproj = (const float*)d_in[2];   // [2048,2048]
    float* out = (float*)d_out;                   // [2,2048,2048]

    float* qkv = nullptr;
    float* y = nullptr;
    cudaGetSymbolAddress((void**)&qkv, g_qkv);
    cudaGetSymbolAddress((void**)&y, g_y);

    cudaFuncSetAttribute(flash_attn, cudaFuncAttributeMaxDynamicSharedMemorySize,
                         FLASH_SMEM);

    // 1) qkv = x @ Wqkv^T : [4096,2048] x [6144,2048]^T
    {
        dim3 grid(QKV_C / BN, BT_ / BM);
        sgemm_nt<<<grid, 256>>>(x, Wqkv, qkv, BT_, QKV_C, C_);
    }
    // 2) flash attention -> y [B,T,C]
    {
        dim3 grid(T_ / FROWS, H_, B_);
        flash_attn<<<grid, 256, FLASH_SMEM>>>(qkv, y);
    }
    // 3) out = y @ Wproj^T : [4096,2048] x [2048,2048]^T
    {
        dim3 grid(C_ / BN, BT_ / BM);
        sgemm_nt<<<grid, 256>>>(y, Wproj, out, BT_, C_, C_);
    }
}

// round 4
// speedup vs baseline: 1.0009x; 1.0005x over previous
#include <cuda_runtime.h>
#include <cuda_bf16.h>

// Shapes (fixed for this problem)
#define B_  2
#define T_  2048
#define C_  2048          // d_model
#define H_  16
#define DH_ 128           // head dim
#define BT_ (B_ * T_)     // 4096 rows
#define QKV_C (3 * C_)    // 6144

// Scratch (device globals — no allocation)
__device__ float g_qkv[(size_t)B_ * T_ * QKV_C];  // 96 MB
__device__ float g_y[(size_t)B_ * T_ * C_];       // 32 MB

// ============================================================================
// SGEMM: C[M,N] = A[M,K] @ B[N,K]^T   (A, B row-major; K contiguous in both)
// 128x128 block tile, BK=8, 256 threads, 8x8 per thread.
// ============================================================================
#define BM 128
#define BN 128
#define BK 8
#define TM 8
#define TN 8

__global__ __launch_bounds__(256, 2)
void sgemm_nt(const float* __restrict__ A, const float* __restrict__ Bm,
              float* __restrict__ C, int M, int N, int K) {
    __shared__ float As[BK][BM];
    __shared__ float Bs[BK][BN];

    const int tid = threadIdx.x;
    const int ty = tid >> 4;          // 0..15
    const int tx = tid & 15;          // 0..15
    const int bm = blockIdx.y * BM;
    const int bn = blockIdx.x * BN;

    // global-load mapping: one float4 of A and one of B per thread per k-tile
    const int lrow = tid >> 1;        // 0..127
    const int lcol = (tid & 1) * 4;   // 0 or 4

    const float* Ab = A + (size_t)bm * K;
    const float* Bb = Bm + (size_t)bn * K;

    float acc[TM][TN];
    #pragma unroll
    for (int i = 0; i < TM; i++)
        #pragma unroll
        for (int j = 0; j < TN; j++) acc[i][j] = 0.f;

    for (int k0 = 0; k0 < K; k0 += BK) {
        float4 av = *(const float4*)(Ab + (size_t)lrow * K + k0 + lcol);
        float4 bv = *(const float4*)(Bb + (size_t)lrow * K + k0 + lcol);
        As[lcol + 0][lrow] = av.x; As[lcol + 1][lrow] = av.y;
        As[lcol + 2][lrow] = av.z; As[lcol + 3][lrow] = av.w;
        Bs[lcol + 0][lrow] = bv.x; Bs[lcol + 1][lrow] = bv.y;
        Bs[lcol + 2][lrow] = bv.z; Bs[lcol + 3][lrow] = bv.w;
        __syncthreads();

        #pragma unroll
        for (int kk = 0; kk < BK; kk++) {
            float a[TM], b[TN];
            float4 a0 = *(const float4*)&As[kk][ty * TM];
            float4 a1 = *(const float4*)&As[kk][ty * TM + 4];
            float4 b0 = *(const float4*)&Bs[kk][tx * TN];
            float4 b1 = *(const float4*)&Bs[kk][tx * TN + 4];
            a[0]=a0.x; a[1]=a0.y; a[2]=a0.z; a[3]=a0.w;
            a[4]=a1.x; a[5]=a1.y; a[6]=a1.z; a[7]=a1.w;
            b[0]=b0.x; b[1]=b0.y; b[2]=b0.z; b[3]=b0.w;
            b[4]=b1.x; b[5]=b1.y; b[6]=b1.z; b[7]=b1.w;
            #pragma unroll
            for (int i = 0; i < TM; i++)
                #pragma unroll
                for (int j = 0; j < TN; j++)
                    acc[i][j] = fmaf(a[i], b[j], acc[i][j]);
        }
        __syncthreads();
    }

    #pragma unroll
    for (int i = 0; i < TM; i++) {
        float* crow = C + (size_t)(bm + ty * TM + i) * N + bn + tx * TN;
        ((float4*)crow)[0] = make_float4(acc[i][0], acc[i][1], acc[i][2], acc[i][3]);
        ((float4*)crow)[1] = make_float4(acc[i][4], acc[i][5], acc[i][6], acc[i][7]);
    }
}

// ============================================================================
// Flash attention (causal, online softmax), fp32.
// grid: (T/64, H, B), 256 threads (16x16). Q-tile 64x128, K-tile 64.
// smem strides padded: QKV rows 132 floats (8-way max conflict on K-col reads),
// S rows 65 floats (conflict-free row scans).
// ============================================================================
#define FROWS 64
#define QSTRIDE 132
#define SSTRIDE 65

extern __shared__ float fsm[];

__global__ __launch_bounds__(256, 1)
void flash_attn(const float* __restrict__ qkv, float* __restrict__ y) {
    const int qt = blockIdx.x;
    const int h  = blockIdx.y;
    const int b  = blockIdx.z;
    const int tid = threadIdx.x;
    const int ty = tid >> 4;   // 0..15  (row group of 4)
    const int tx = tid & 15;   // 0..15

    float* Qs = fsm;                       // [64][132]
    float* Ks = Qs + FROWS * QSTRIDE;      // [64][132]
    float* Vs = Ks + FROWS * QSTRIDE;      // [64][132]
    float* Ss = Vs + FROWS * QSTRIDE;      // [64][65]
    float* ms = Ss + FROWS * SSTRIDE;      // [64]
    float* ls = ms + FROWS;                // [64]
    float* rs = ls + FROWS;                // [64]

    const float scale = 0.08838834764831845f;  // 1/sqrt(128)

    const float* qb = qkv + ((size_t)b * T_) * QKV_C + h * DH_;
    const float* kb = qb + C_;
    const float* vb = qb + 2 * C_;

    // Load Q tile: 64 rows x 128 floats = 2048 float4 / 256 thr = 8 each
    for (int i = tid; i < FROWS * 32; i += 256) {
        int r = i >> 5, c4 = i & 31;
        *(float4*)(Qs + r * QSTRIDE + c4 * 4) =
            ((const float4*)(qb + (size_t)(qt * FROWS + r) * QKV_C))[c4];
    }
    if (tid < FROWS) { ms[tid] = -1e30f; ls[tid] = 0.f; }

    float o[4][8];
    #pragma unroll
    for (int i = 0; i < 4; i++)
        #pragma unroll
        for (int j = 0; j < 8; j++) o[i][j] = 0.f;

    for (int kt = 0; kt <= qt; kt++) {
        __syncthreads();   // protects Ss/Ks/Vs from previous iter + Q/stats on iter 0
        for (int i = tid; i < FROWS * 32; i += 256) {
            int r = i >> 5, c4 = i & 31;
            *(float4*)(Ks + r * QSTRIDE + c4 * 4) =
                ((const float4*)(kb + (size_t)(kt * FROWS + r) * QKV_C))[c4];
            *(float4*)(Vs + r * QSTRIDE + c4 * 4) =
                ((const float4*)(vb + (size_t)(kt * FROWS + r) * QKV_C))[c4];
        }
        __syncthreads();

        // ---- S = Q K^T (thread: rows ty*4.., cols tx*4..) ----
        float s[4][4];
        #pragma unroll
        for (int i = 0; i < 4; i++)
            #pragma unroll
            for (int j = 0; j < 4; j++) s[i][j] = 0.f;

        for (int d4 = 0; d4 < 32; d4++) {
            float4 qv[4], kv[4];
            #pragma unroll
            for (int i = 0; i < 4; i++)
                qv[i] = *(const float4*)(Qs + (ty * 4 + i) * QSTRIDE + d4 * 4);
            #pragma unroll
            for (int j = 0; j < 4; j++)
                kv[j] = *(const float4*)(Ks + (tx * 4 + j) * QSTRIDE + d4 * 4);
            #pragma unroll
            for (int i = 0; i < 4; i++)
                #pragma unroll
                for (int j = 0; j < 4; j++) {
                    s[i][j] = fmaf(qv[i].x, kv[j].x, s[i][j]);
                    s[i][j] = fmaf(qv[i].y, kv[j].y, s[i][j]);
                    s[i][j] = fmaf(qv[i].z, kv[j].z, s[i][j]);
                    s[i][j] = fmaf(qv[i].w, kv[j].w, s[i][j]);
                }
        }

        // scale + causal mask, write to Ss
        #pragma unroll
        for (int i = 0; i < 4; i++) {
            int gq = qt * FROWS + ty * 4 + i;
            #pragma unroll
            for (int j = 0; j < 4; j++) {
                int gk = kt * FROWS + tx * 4 + j;
                float v = s[i][j] * scale;
                if (gk > gq) v = -1e30f;
                Ss[(ty * 4 + i) * SSTRIDE + tx * 4 + j] = v;
            }
        }
        __syncthreads();

        // ---- online softmax, one thread per row ----
        if (tid < FROWS) {
            float mold = ms[tid];
            float mloc = mold;
            float* row = Ss + tid * SSTRIDE;
            #pragma unroll 8
            for (int c = 0; c < FROWS; c++) mloc = fmaxf(mloc, row[c]);
            float rsc = __expf(mold - mloc);
            float sum = 0.f;
            #pragma unroll 8
            for (int c = 0; c < FROWS; c++) {
                float p = __expf(row[c] - mloc);
                row[c] = p;
                sum += p;
            }
            ms[tid] = mloc;
            ls[tid] = ls[tid] * rsc + sum;
            rs[tid] = rsc;
        }
        __syncthreads();

        // ---- rescale O, accumulate O += P @ V (thread cols tx*8..) ----
        #pragma unroll
        for (int i = 0; i < 4; i++) {
            float f = rs[ty * 4 + i];
            #pragma unroll
            for (int j = 0; j < 8; j++) o[i][j] *= f;
        }
        for (int kk = 0; kk < FROWS; kk++) {
            float p[4];
            #pragma unroll
            for (int i = 0; i < 4; i++) p[i] = Ss[(ty * 4 + i) * SSTRIDE + kk];
            float4 v0 = *(const float4*)(Vs + kk * QSTRIDE + tx * 8);
            float4 v1 = *(const float4*)(Vs + kk * QSTRIDE + tx * 8 + 4);
            #pragma unroll
            for (int i = 0; i < 4; i++) {
                o[i][0] = fmaf(p[i], v0.x, o[i][0]);
                o[i][1] = fmaf(p[i], v0.y, o[i][1]);
                o[i][2] = fmaf(p[i], v0.z, o[i][2]);
                o[i][3] = fmaf(p[i], v0.w, o[i][3]);
                o[i][4] = fmaf(p[i], v1.x, o[i][4]);
                o[i][5] = fmaf(p[i], v1.y, o[i][5]);
                o[i][6] = fmaf(p[i], v1.z, o[i][6]);
                o[i][7] = fmaf(p[i], v1.w, o[i][7]);
            }
        }
    }
    __syncthreads();

    // write y[b, t, h*128 + col]  (BTC layout, ready for proj GEMM)
    #pragma unroll
    for (int i = 0; i < 4; i++) {
        int r = ty * 4 + i;
        float inv = 1.0f / ls[r];
        float* yrow = y + ((size_t)b * T_ + qt * FROWS + r) * C_ + h * DH_ + tx * 8;
        ((float4*)yrow)[0] = make_float4(o[i][0]*inv, o[i][1]*inv, o[i][2]*inv, o[i][3]*inv);
        ((float4*)yrow)[1] = make_float4(o[i][4]*inv, o[i][5]*inv, o[i][6]*inv, o[i][7]*inv);
    }
}

// ============================================================================
// launch
// ============================================================================
static const int FLASH_SMEM =
    (3 * FROWS * QSTRIDE + FROWS * SSTRIDE + 3 * FROWS) * (int)sizeof(float);

extern "C" void kernel_launch(void* const* d_in, const int* in_sizes, int n_in,
                              void* d_out, int out_size) {
    const float* x     = (const float*)d_in[0];   // [2,2048,2048]
    const float* Wqkv  = (const float*)d_in[1];   // [6144,2048]
    const float* Wproj = (const float*)d_in[2];   // [2048,2048]
    float* out = (float*)d_out;                   // [2,2048,2048]

    float* qkv = nullptr;
    float* y = nullptr;
    cudaGetSymbolAddress((void**)&qkv, g_qkv);
    cudaGetSymbolAddress((void**)&y, g_y);

    cudaFuncSetAttribute(flash_attn, cudaFuncAttributeMaxDynamicSharedMemorySize,
                         FLASH_SMEM);

    // 1) qkv = x @ Wqkv^T : [4096,2048] x [6144,2048]^T
    {
        dim3 grid(QKV_C / BN, BT_ / BM);
        sgemm_nt<<<grid, 256>>>(x, Wqkv, qkv, BT_, QKV_C, C_);
    }
    // 2) flash attention -> y [B,T,C]
    {
        dim3 grid(T_ / FROWS, H_, B_);
        flash_attn<<<grid, 256, FLASH_SMEM>>>(qkv, y);
    }
    // 3) out = y @ Wproj^T : [4096,2048] x [2048,2048]^T
    {
        dim3 grid(C_ / BN, BT_ / BM);
        sgemm_nt<<<grid, 256>>>(y, Wproj, out, BT_, C_, C_);
    }
}

// round 5
// speedup vs baseline: 1.0018x; 1.0009x over previous
#include <cuda_runtime.h>
#include <cuda_bf16.h>

// Shapes (fixed for this problem)
#define B_  2
#define T_  2048
#define C_  2048          // d_model
#define H_  16
#define DH_ 128           // head dim
#define BT_ (B_ * T_)     // 4096 rows
#define QKV_C (3 * C_)    // 6144

// Scratch (device globals — no allocation)
__device__ float g_qkv[(size_t)B_ * T_ * QKV_C];  // 96 MB
__device__ float g_y[(size_t)B_ * T_ * C_];       // 32 MB

// ============================================================================
// SGEMM: C[M,N] = A[M,K] @ B[N,K]^T   (A, B row-major; K contiguous in both)
// 128x128 block tile, BK=8, 256 threads, 8x8 per thread.
// ============================================================================
#define BM 128
#define BN 128
#define BK 8
#define TM 8
#define TN 8

__global__ __launch_bounds__(256, 2)
void sgemm_nt(const float* __restrict__ A, const float* __restrict__ Bm,
              float* __restrict__ C, int M, int N, int K) {
    __shared__ float As[BK][BM];
    __shared__ float Bs[BK][BN];

    const int tid = threadIdx.x;
    const int ty = tid >> 4;          // 0..15
    const int tx = tid & 15;          // 0..15
    const int bm = blockIdx.y * BM;
    const int bn = blockIdx.x * BN;

    // global-load mapping: one float4 of A and one of B per thread per k-tile
    const int lrow = tid >> 1;        // 0..127
    const int lcol = (tid & 1) * 4;   // 0 or 4

    const float* Ab = A + (size_t)bm * K;
    const float* Bb = Bm + (size_t)bn * K;

    float acc[TM][TN];
    #pragma unroll
    for (int i = 0; i < TM; i++)
        #pragma unroll
        for (int j = 0; j < TN; j++) acc[i][j] = 0.f;

    for (int k0 = 0; k0 < K; k0 += BK) {
        float4 av = *(const float4*)(Ab + (size_t)lrow * K + k0 + lcol);
        float4 bv = *(const float4*)(Bb + (size_t)lrow * K + k0 + lcol);
        As[lcol + 0][lrow] = av.x; As[lcol + 1][lrow] = av.y;
        As[lcol + 2][lrow] = av.z; As[lcol + 3][lrow] = av.w;
        Bs[lcol + 0][lrow] = bv.x; Bs[lcol + 1][lrow] = bv.y;
        Bs[lcol + 2][lrow] = bv.z; Bs[lcol + 3][lrow] = bv.w;
        __syncthreads();

        #pragma unroll
        for (int kk = 0; kk < BK; kk++) {
            float a[TM], b[TN];
            float4 a0 = *(const float4*)&As[kk][ty * TM];
            float4 a1 = *(const float4*)&As[kk][ty * TM + 4];
            float4 b0 = *(const float4*)&Bs[kk][tx * TN];
            float4 b1 = *(const float4*)&Bs[kk][tx * TN + 4];
            a[0]=a0.x; a[1]=a0.y; a[2]=a0.z; a[3]=a0.w;
            a[4]=a1.x; a[5]=a1.y; a[6]=a1.z; a[7]=a1.w;
            b[0]=b0.x; b[1]=b0.y; b[2]=b0.z; b[3]=b0.w;
            b[4]=b1.x; b[5]=b1.y; b[6]=b1.z; b[7]=b1.w;
            #pragma unroll
            for (int i = 0; i < TM; i++)
                #pragma unroll
                for (int j = 0; j < TN; j++)
                    acc[i][j] = fmaf(a[i], b[j], acc[i][j]);
        }
        __syncthreads();
    }

    #pragma unroll
    for (int i = 0; i < TM; i++) {
        float* crow = C + (size_t)(bm + ty * TM + i) * N + bn + tx * TN;
        ((float4*)crow)[0] = make_float4(acc[i][0], acc[i][1], acc[i][2], acc[i][3]);
        ((float4*)crow)[1] = make_float4(acc[i][4], acc[i][5], acc[i][6], acc[i][7]);
    }
}

// ============================================================================
// Flash attention (causal, online softmax), fp32.
// grid: (T/64, H, B), 256 threads (16x16). Q-tile 64x128, K-tile 64.
// smem strides padded: QKV rows 132 floats (8-way max conflict on K-col reads),
// S rows 65 floats (conflict-free row scans).
// ============================================================================
#define FROWS 64
#define QSTRIDE 132
#define SSTRIDE 65

extern __shared__ float fsm[];

__global__ __launch_bounds__(256, 1)
void flash_attn(const float* __restrict__ qkv, float* __restrict__ y) {
    const int qt = blockIdx.x;
    const int h  = blockIdx.y;
    const int b  = blockIdx.z;
    const int tid = threadIdx.x;
    const int ty = tid >> 4;   // 0..15  (row group of 4)
    const int tx = tid & 15;   // 0..15

    float* Qs = fsm;                       // [64][132]
    float* Ks = Qs + FROWS * QSTRIDE;      // [64][132]
    float* Vs = Ks + FROWS * QSTRIDE;      // [64][132]
    float* Ss = Vs + FROWS * QSTRIDE;      // [64][65]
    float* ms = Ss + FROWS * SSTRIDE;      // [64]
    float* ls = ms + FROWS;                // [64]
    float* rs = ls + FROWS;                // [64]

    const float scale = 0.08838834764831845f;  // 1/sqrt(128)

    const float* qb = qkv + ((size_t)b * T_) * QKV_C + h * DH_;
    const float* kb = qb + C_;
    const float* vb = qb + 2 * C_;

    // Load Q tile: 64 rows x 128 floats = 2048 float4 / 256 thr = 8 each
    for (int i = tid; i < FROWS * 32; i += 256) {
        int r = i >> 5, c4 = i & 31;
        *(float4*)(Qs + r * QSTRIDE + c4 * 4) =
            ((const float4*)(qb + (size_t)(qt * FROWS + r) * QKV_C))[c4];
    }
    if (tid < FROWS) { ms[tid] = -1e30f; ls[tid] = 0.f; }

    float o[4][8];
    #pragma unroll
    for (int i = 0; i < 4; i++)
        #pragma unroll
        for (int j = 0; j < 8; j++) o[i][j] = 0.f;

    for (int kt = 0; kt <= qt; kt++) {
        __syncthreads();   // protects Ss/Ks/Vs from previous iter + Q/stats on iter 0
        for (int i = tid; i < FROWS * 32; i += 256) {
            int r = i >> 5, c4 = i & 31;
            *(float4*)(Ks + r * QSTRIDE + c4 * 4) =
                ((const float4*)(kb + (size_t)(kt * FROWS + r) * QKV_C))[c4];
            *(float4*)(Vs + r * QSTRIDE + c4 * 4) =
                ((const float4*)(vb + (size_t)(kt * FROWS + r) * QKV_C))[c4];
        }
        __syncthreads();

        // ---- S = Q K^T (thread: rows ty*4.., cols tx*4..) ----
        float s[4][4];
        #pragma unroll
        for (int i = 0; i < 4; i++)
            #pragma unroll
            for (int j = 0; j < 4; j++) s[i][j] = 0.f;

        for (int d4 = 0; d4 < 32; d4++) {
            float4 qv[4], kv[4];
            #pragma unroll
            for (int i = 0; i < 4; i++)
                qv[i] = *(const float4*)(Qs + (ty * 4 + i) * QSTRIDE + d4 * 4);
            #pragma unroll
            for (int j = 0; j < 4; j++)
                kv[j] = *(const float4*)(Ks + (tx * 4 + j) * QSTRIDE + d4 * 4);
            #pragma unroll
            for (int i = 0; i < 4; i++)
                #pragma unroll
                for (int j = 0; j < 4; j++) {
                    s[i][j] = fmaf(qv[i].x, kv[j].x, s[i][j]);
                    s[i][j] = fmaf(qv[i].y, kv[j].y, s[i][j]);
                    s[i][j] = fmaf(qv[i].z, kv[j].z, s[i][j]);
                    s[i][j] = fmaf(qv[i].w, kv[j].w, s[i][j]);
                }
        }

        // scale + causal mask, write to Ss
        #pragma unroll
        for (int i = 0; i < 4; i++) {
            int gq = qt * FROWS + ty * 4 + i;
            #pragma unroll
            for (int j = 0; j < 4; j++) {
                int gk = kt * FROWS + tx * 4 + j;
                float v = s[i][j] * scale;
                if (gk > gq) v = -1e30f;
                Ss[(ty * 4 + i) * SSTRIDE + tx * 4 + j] = v;
            }
        }
        __syncthreads();

        // ---- online softmax, one thread per row ----
        if (tid < FROWS) {
            float mold = ms[tid];
            float mloc = mold;
            float* row = Ss + tid * SSTRIDE;
            #pragma unroll 8
            for (int c = 0; c < FROWS; c++) mloc = fmaxf(mloc, row[c]);
            float rsc = __expf(mold - mloc);
            float sum = 0.f;
            #pragma unroll 8
            for (int c = 0; c < FROWS; c++) {
                float p = __expf(row[c] - mloc);
                row[c] = p;
                sum += p;
            }
            ms[tid] = mloc;
            ls[tid] = ls[tid] * rsc + sum;
            rs[tid] = rsc;
        }
        __syncthreads();

        // ---- rescale O, accumulate O += P @ V (thread cols tx*8..) ----
        #pragma unroll
        for (int i = 0; i < 4; i++) {
            float f = rs[ty * 4 + i];
            #pragma unroll
            for (int j = 0; j < 8; j++) o[i][j] *= f;
        }
        for (int kk = 0; kk < FROWS; kk++) {
            float p[4];
            #pragma unroll
            for (int i = 0; i < 4; i++) p[i] = Ss[(ty * 4 + i) * SSTRIDE + kk];
            float4 v0 = *(const float4*)(Vs + kk * QSTRIDE + tx * 8);
            float4 v1 = *(const float4*)(Vs + kk * QSTRIDE + tx * 8 + 4);
            #pragma unroll
            for (int i = 0; i < 4; i++) {
                o[i][0] = fmaf(p[i], v0.x, o[i][0]);
                o[i][1] = fmaf(p[i], v0.y, o[i][1]);
                o[i][2] = fmaf(p[i], v0.z, o[i][2]);
                o[i][3] = fmaf(p[i], v0.w, o[i][3]);
                o[i][4] = fmaf(p[i], v1.x, o[i][4]);
                o[i][5] = fmaf(p[i], v1.y, o[i][5]);
                o[i][6] = fmaf(p[i], v1.z, o[i][6]);
                o[i][7] = fmaf(p[i], v1.w, o[i][7]);
            }
        }
    }
    __syncthreads();

    // write y[b, t, h*128 + col]  (BTC layout, ready for proj GEMM)
    #pragma unroll
    for (int i = 0; i < 4; i++) {
        int r = ty * 4 + i;
        float inv = 1.0f / ls[r];
        float* yrow = y + ((size_t)b * T_ + qt * FROWS + r) * C_ + h * DH_ + tx * 8;
        ((float4*)yrow)[0] = make_float4(o[i][0]*inv, o[i][1]*inv, o[i][2]*inv, o[i][3]*inv);
        ((float4*)yrow)[1] = make_float4(o[i][4]*inv, o[i][5]*inv, o[i][6]*inv, o[i][7]*inv);
    }
}

// ============================================================================
// launch
// ============================================================================
static const int FLASH_SMEM =
    (3 * FROWS * QSTRIDE + FROWS * SSTRIDE + 3 * FROWS) * (int)sizeof(float);

extern "C" void kernel_launch(void* const* d_in, const int* in_sizes, int n_in,
                              void* d_out, int out_size) {
    const float* x     = (const float*)d_in[0];   // [2,2048,2048]
    const float* Wqkv  = (const float*)d_in[1];   // [6144,2048]
    const float* Wproj = (const float*)d_in[2];   // [2048,2048]
    float* out = (float*)d_out;                   // [2,2048,2048]

    float* qkv = nullptr;
    float* y = nullptr;
    cudaGetSymbolAddress((void**)&qkv, g_qkv);
    cudaGetSymbolAddress((void**)&y, g_y);

    cudaFuncSetAttribute(flash_attn, cudaFuncAttributeMaxDynamicSharedMemorySize,
                         FLASH_SMEM);

    // 1) qkv = x @ Wqkv^T : [4096,2048] x [6144,2048]^T
    {
        dim3 grid(QKV_C / BN, BT_ / BM);
        sgemm_nt<<<grid, 256>>>(x, Wqkv, qkv, BT_, QKV_C, C_);
    }
    // 2) flash attention -> y [B,T,C]
    {
        dim3 grid(T_ / FROWS, H_, B_);
        flash_attn<<<grid, 256, FLASH_SMEM>>>(qkv, y);
    }
    // 3) out = y @ Wproj^T : [4096,2048] x [2048,2048]^T
    {
        dim3 grid(C_ / BN, BT_ / BM);
        sgemm_nt<<<grid, 256>>>(y, Wproj, out, BT_, C_, C_);
    }
}